// round 17
// baseline (speedup 1.0000x reference)
#include <cuda_runtime.h>
#include <cuda_fp16.h>
#include <cstdint>
#include <math.h>

// Problem constants
#define Bc   4
#define Lc   1024
#define Dc   1024
#define Hc   16
#define DHc  64
#define FFc  4096
#define Mrows (Bc*Lc)        // 4096
#define PER_T ((size_t)Bc*Hc*Lc*DHc)   // 4194304

// ---------------- scratch (static device memory) ----------------
__device__ float g_tmp[(size_t)Mrows * Dc];
__device__ float g_h[(size_t)Mrows * Dc];
__device__ float g_bqkv[3 * Dc];

__device__ __half g_qkv0[3 * PER_T];             // q,k,v fp16 [B,H,L,DH] (q pre-scaled by 1/8)
__device__ __half g_x0[(size_t)Mrows * Dc];
__device__ __half g_c0[(size_t)Mrows * Dc];
__device__ __half g_h0[(size_t)Mrows * Dc];
__device__ __half g_mid0[(size_t)Mrows * FFc];

__device__ __half g_wqkv[(size_t)3 * Dc * Dc];   // [3072,1024] (transposed fp16)
__device__ __half g_wo[(size_t)Dc * Dc];         // [1024,1024]
__device__ __half g_w1t[(size_t)FFc * Dc];       // [4096,1024]
__device__ __half g_w2t[(size_t)Dc * FFc];       // [1024,4096]

// ---------------- helpers ----------------
__device__ __forceinline__ uint32_t smem_u32(const void* p) {
    uint32_t a;
    asm("{ .reg .u64 t; cvta.to.shared.u64 t, %1; cvt.u32.u64 %0, t; }" : "=r"(a) : "l"(p));
    return a;
}
__device__ __forceinline__ void cpa16(uint32_t saddr, const void* g) {
    asm volatile("cp.async.cg.shared.global [%0], [%1], 16;" :: "r"(saddr), "l"(g));
}
// bulk async copy gmem->smem, completion via mbarrier complete_tx (sm_90 baseline)
__device__ __forceinline__ void cpbulk(uint32_t dst, const void* src, uint32_t bytes,
                                       uint32_t mbar) {
    asm volatile(
        "cp.async.bulk.shared::cluster.global.mbarrier::complete_tx::bytes [%0], [%1], %2, [%3];"
        :: "r"(dst), "l"(src), "r"(bytes), "r"(mbar) : "memory");
}
__device__ __forceinline__ void mma16816(float* c, const uint32_t* a, const uint32_t* b) {
    asm volatile(
        "mma.sync.aligned.m16n8k16.row.col.f32.f16.f16.f32 "
        "{%0,%1,%2,%3}, {%4,%5,%6,%7}, {%8,%9}, {%0,%1,%2,%3};\n"
        : "+f"(c[0]), "+f"(c[1]), "+f"(c[2]), "+f"(c[3])
        : "r"(a[0]), "r"(a[1]), "r"(a[2]), "r"(a[3]), "r"(b[0]), "r"(b[1]));
}
__device__ __forceinline__ uint32_t pk_f16x2(float lo, float hi) {
    uint32_t d;
    asm("cvt.rn.f16x2.f32 %0, %1, %2;" : "=r"(d) : "f"(hi), "f"(lo));
    return d;
}
#define LDSM_X4(r0, r1, r2, r3, addr) \
    asm volatile("ldmatrix.sync.aligned.m8n8.x4.shared.b16 {%0,%1,%2,%3}, [%4];" \
        : "=r"(r0), "=r"(r1), "=r"(r2), "=r"(r3) : "r"(addr))
#define LDSM_X4_T(r0, r1, r2, r3, addr) \
    asm volatile("ldmatrix.sync.aligned.m8n8.x4.trans.shared.b16 {%0,%1,%2,%3}, [%4];" \
        : "=r"(r0), "=r"(r1), "=r"(r2), "=r"(r3) : "r"(addr))

#define MBAR_INIT(a, n) asm volatile("mbarrier.init.shared.b64 [%0], %1;" :: "r"(a), "r"((uint32_t)(n)) : "memory")
#define MBAR_ARRIVE(a)  asm volatile("mbarrier.arrive.shared.b64 _, [%0];" :: "r"(a) : "memory")
#define MBAR_EXPECT_TX(a, n) asm volatile("mbarrier.arrive.expect_tx.shared.b64 _, [%0], %1;" :: "r"(a), "r"((uint32_t)(n)) : "memory")
#define MBAR_WAIT(a, ph) do {                                                         \
    uint32_t _m = (a), _p = (ph), _d;                                                 \
    asm volatile("{ .reg .pred p; mbarrier.try_wait.parity.acquire.cta.shared::cta.b64 p, [%1], %2; selp.b32 %0,1,0,p; }" \
        : "=r"(_d) : "r"(_m), "r"(_p) : "memory");                                    \
    if (!_d) {                                                                        \
        asm volatile("{ .reg .pred P1; WL_%=: mbarrier.try_wait.parity.acquire.cta.shared::cta.b64 P1, [%0], %1, 0x989680; @P1 bra.uni WD_%=; bra.uni WL_%=; WD_%=: }" \
            :: "r"(_m), "r"(_p) : "memory");                                          \
    }                                                                                 \
} while (0)

// ---------------- HMMA GEMM (1-term): C[M,N] = A[M,K] @ W^T  (W is [N,K] fp16) -----
// Block tile 128x128, K-chunk 64. 9 warps: 8 consumers (2x4, warp tile 64x32) + 1
// producer issuing cp.async.bulk row copies. 3-stage mbarrier pipeline
// (full: expect_tx 32768 B; empty: 8 warp-arrivals). No per-iter __syncthreads.
// OUTM: 0 = plain fp32 +bias; 1 = QKV head-split scatter fp16 (q scaled 1/8);
//       2 = relu + single fp16 S0
#define PADB 144                // bytes per smem row (64 fp16 data + 16 pad)
#define TILEB (128 * PADB)      // 18432 bytes per tile
#define STG   (2 * TILEB)       // 36864 bytes per stage (A, W)
#define NSTG  3
#define OFF_MB (NSTG * STG)     // 110592
#define GSMEM  (OFF_MB + 64)

template<int OUTM>
__global__ __launch_bounds__(288, 1) void gemm1(
    const __half* __restrict__ A,
    const __half* __restrict__ W,
    const float* __restrict__ bias, float* __restrict__ C,
    __half* __restrict__ S0,
    int K, int N)
{
    extern __shared__ __align__(16) char smem[];
    const uint32_t sb = smem_u32(smem);
    const int tid = threadIdx.x;
    const int wid = tid >> 5;
    const int lid = tid & 31;
    const int col0 = blockIdx.x * 128;
    const int row0 = blockIdx.y * 128;
    const uint32_t mbF = sb + OFF_MB;        // full[s]  at +8s
    const uint32_t mbE = sb + OFF_MB + 24;   // empty[s] at +8s

    if (tid == 0) {
#pragma unroll
        for (int s2 = 0; s2 < NSTG; s2++) {
            MBAR_INIT(mbF + 8 * s2, 1);
            MBAR_INIT(mbE + 8 * s2, 8);
        }
    }
    __syncthreads();

    const int NC = K >> 6;

    if (wid == 8) {
        // ---------------- producer warp ----------------
        const __half* gpA = A + ((size_t)row0 + lid) * K;
        const __half* gpW = W + ((size_t)col0 + lid) * K;
        int ep0 = 0, ep1 = 0, ep2 = 0;
        for (int c = 0; c < NC; c++) {
            int st2 = c % 3;
            if (c >= 3) {
                if (st2 == 0)      { MBAR_WAIT(mbE + 0,  ep0); ep0 ^= 1; }
                else if (st2 == 1) { MBAR_WAIT(mbE + 8,  ep1); ep1 ^= 1; }
                else               { MBAR_WAIT(mbE + 16, ep2); ep2 ^= 1; }
            }
            const uint32_t fb = mbF + 8 * st2;
            if (lid == 0) MBAR_EXPECT_TX(fb, 32768);
            const int k0 = c << 6;
            uint32_t dstA = sb + st2 * STG + lid * PADB;
#pragma unroll
            for (int j = 0; j < 4; j++) {
                cpbulk(dstA + j * 32 * PADB,         gpA + (size_t)(32 * j) * K + k0, 128, fb);
                cpbulk(dstA + TILEB + j * 32 * PADB, gpW + (size_t)(32 * j) * K + k0, 128, fb);
            }
        }
        return;
    }

    // ---------------- consumer warps (0..7) ----------------
    const int wm = wid >> 2;          // 0..1
    const int wn = wid & 3;           // 0..3
    const int g = lid >> 2;           // 0..7
    const int t = lid & 3;            // 0..3
    const int r8 = lid & 7;           // ldmatrix row
    const int mm = lid >> 3;          // ldmatrix matrix id

    float acc[4][4][4];
#pragma unroll
    for (int i = 0; i < 4; i++)
#pragma unroll
        for (int j = 0; j < 4; j++)
#pragma unroll
            for (int q = 0; q < 4; q++) acc[i][j][q] = 0.f;

    const uint32_t aOff = (uint32_t)((wm * 64 + (mm & 1) * 8 + r8) * PADB + (mm >> 1) * 16);
    const uint32_t wOff = (uint32_t)((wn * 32 + (mm >> 1) * 8 + r8) * PADB + (mm & 1) * 16);

    int fp0 = 0, fp1 = 0, fp2 = 0;
    for (int c = 0; c < NC; c++) {
        int st2 = c % 3;
        if (st2 == 0)      { MBAR_WAIT(mbF + 0,  fp0); fp0 ^= 1; }
        else if (st2 == 1) { MBAR_WAIT(mbF + 8,  fp1); fp1 ^= 1; }
        else               { MBAR_WAIT(mbF + 16, fp2); fp2 ^= 1; }

        const uint32_t sAu = sb + st2 * STG;
        const uint32_t sWu = sAu + TILEB;
#pragma unroll
        for (int ks = 0; ks < 4; ks++) {
            uint32_t af[4][4], wf[4][2];
            LDSM_X4(wf[0][0], wf[0][1], wf[1][0], wf[1][1], sWu + wOff + ks * 32);
            LDSM_X4(wf[2][0], wf[2][1], wf[3][0], wf[3][1], sWu + wOff + 16 * PADB + ks * 32);
#pragma unroll
            for (int i = 0; i < 4; i++)
                LDSM_X4(af[i][0], af[i][1], af[i][2], af[i][3],
                        sAu + aOff + i * 16 * PADB + ks * 32);
#pragma unroll
            for (int i = 0; i < 4; i++)
#pragma unroll
                for (int j = 0; j < 4; j++)
                    mma16816(acc[i][j], af[i], wf[j]);
        }
        if (lid == 0) MBAR_ARRIVE(mbE + 8 * st2);
    }

    // ---------------- epilogue ----------------
#pragma unroll
    for (int i = 0; i < 4; i++) {
        int mg0 = row0 + wm * 64 + i * 16 + g;
#pragma unroll
        for (int rr = 0; rr < 2; rr++) {
            int mg = mg0 + rr * 8;
#pragma unroll
            for (int j = 0; j < 4; j++) {
                int ngc = col0 + wn * 32 + j * 8 + 2 * t;
                float v0 = acc[i][j][rr * 2 + 0] + bias[ngc];
                float v1 = acc[i][j][rr * 2 + 1] + bias[ngc + 1];
                if (OUTM == 0) {
                    float2 o; o.x = v0; o.y = v1;
                    *(float2*)(C + (size_t)mg * N + ngc) = o;
                } else if (OUTM == 1) {
                    int bb = mg >> 10, ll = mg & 1023;
                    int w = ngc >> 10;
                    int head = (ngc >> 6) & 15;
                    int d = ngc & 63;
                    if (w == 0) { v0 *= 0.125f; v1 *= 0.125f; }   // fold 1/sqrt(DH) into q
                    size_t off = (size_t)w * PER_T +
                                 (((size_t)(bb * Hc + head)) * Lc + ll) * DHc + d;
                    *(uint32_t*)(S0 + off) = pk_f16x2(v0, v1);
                } else {
                    v0 = fmaxf(v0, 0.f); v1 = fmaxf(v1, 0.f);
                    *(uint32_t*)(S0 + (size_t)mg * N + ngc) = pk_f16x2(v0, v1);
                }
            }
        }
    }
}

// ---------------- fused prep: 6 weight transposes + x convert + bias concat ---------
__global__ __launch_bounds__(256) void prep_k(
    const float* __restrict__ wq, const float* __restrict__ wk,
    const float* __restrict__ wv, const float* __restrict__ wo,
    const float* __restrict__ w1, const float* __restrict__ w2,
    const float* __restrict__ bq, const float* __restrict__ bk,
    const float* __restrict__ bv, const float* __restrict__ x,
    __half* __restrict__ wqkv, __half* __restrict__ woh,
    __half* __restrict__ w1t, __half* __restrict__ w2t,
    float* __restrict__ bqkv, __half* __restrict__ x0)
{
    __shared__ float tsm[32][33];
    const int f = blockIdx.x;
    if (f >= 16384) {           // bias concat
        int i = (f - 16384) * 256 + threadIdx.x;
        bqkv[i] = (i < 1024) ? bq[i] : ((i < 2048) ? bk[i - 1024] : bv[i - 2048]);
        return;
    }
    if (f >= 12288) {           // x convert
        int i = (f - 12288) * 1024 + threadIdx.x;
#pragma unroll
        for (int j = 0; j < 4; j++)
            x0[i + j * 256] = __float2half(x[i + j * 256]);
        return;
    }
    const float* W; __half* T; int K, N, nb, kb;
    if (f < 4096) {
        int sel = f >> 10, idx = f & 1023;
        W = sel == 0 ? wq : sel == 1 ? wk : sel == 2 ? wv : wo;
        T = sel < 3 ? wqkv + (size_t)sel * Dc * Dc : woh;
        K = Dc; N = Dc;
        nb = (idx & 31) * 32; kb = (idx >> 5) * 32;
    } else if (f < 8192) {
        int idx = f - 4096;
        W = w1; T = w1t; K = Dc; N = FFc;
        nb = (idx & 127) * 32; kb = (idx >> 7) * 32;
    } else {
        int idx = f - 8192;
        W = w2; T = w2t; K = FFc; N = Dc;
        nb = (idx & 31) * 32; kb = (idx >> 5) * 32;
    }
    const int tx = threadIdx.x & 31, ty = threadIdx.x >> 5;
#pragma unroll
    for (int i = 0; i < 4; i++) {
        int k = ty + i * 8;
        tsm[k][tx] = W[(size_t)(kb + k) * N + nb + tx];
    }
    __syncthreads();
#pragma unroll
    for (int i = 0; i < 4; i++) {
        int n = ty + i * 8;
        T[(size_t)(nb + n) * K + kb + tx] = __float2half(tsm[tx][n]);
    }
}

// ---------------- MMA flash attention (fp16, 1-term, ldmatrix, no online max) -----
#define KVSTRIDE 36                   // words per 64-fp16 row (32 data + 4 pad)
#define KVROWB   (KVSTRIDE * 4)       // 144 bytes per row
#define KVTILE   (64 * KVSTRIDE)      // words per tile

__global__ __launch_bounds__(256) void attn_mma_k(
    const __half* __restrict__ qkv0,
    const float* __restrict__ attn_bias, const int* __restrict__ src_mask,
    __half* __restrict__ c0g)
{
    __shared__ __align__(16) uint32_t sK[2 * KVTILE];
    __shared__ __align__(16) uint32_t sV[2 * KVTILE];
    __shared__ int smsk[2][64];

    const int tid = threadIdx.x;
    const int wid = tid >> 5;
    const int lid = tid & 31;
    const int g = lid >> 2;
    const int t = lid & 3;
    const int r8 = lid & 7;
    const int mm = lid >> 3;
    const int bh = blockIdx.y;
    const int b = bh >> 4;
    const int head = bh & 15;
    const int warp_q = blockIdx.x * 128 + wid * 16;

    const uint32_t sKu = smem_u32(sK);
    const uint32_t sVu = smem_u32(sV);
    const uint32_t kOff = (uint32_t)(r8 * KVROWB + (mm & 1) * 16 + (mm >> 1) * 32);
    const uint32_t vOff = (uint32_t)(((mm & 1) * 8 + r8) * KVROWB + (mm >> 1) * 16);

    // ---- Q fragments (held in registers whole kernel; q pre-scaled by 1/8) ----
    const __half* q0p = qkv0 + ((size_t)bh * Lc + warp_q) * DHc;
    uint32_t q0f[4][4];
#pragma unroll
    for (int kk = 0; kk < 4; kk++) {
        int c0 = kk * 16 + 2 * t;
        q0f[kk][0] = *(const uint32_t*)(q0p + (size_t)g * DHc + c0);
        q0f[kk][1] = *(const uint32_t*)(q0p + (size_t)(g + 8) * DHc + c0);
        q0f[kk][2] = *(const uint32_t*)(q0p + (size_t)g * DHc + c0 + 8);
        q0f[kk][3] = *(const uint32_t*)(q0p + (size_t)(g + 8) * DHc + c0 + 8);
    }

    const __half* kbase = qkv0 + PER_T + (size_t)bh * Lc * DHc;
    const __half* vbase = qkv0 + 2 * PER_T + (size_t)bh * Lc * DHc;
    const float* brow0 = attn_bias + ((size_t)b * Lc + warp_q + g) * Lc;
    const float* brow1 = attn_bias + ((size_t)b * Lc + warp_q + g + 8) * Lc;

    auto issueKV = [&](int kt, int st) {
#pragma unroll
        for (int i = 0; i < 2; i++) {
            int idx = tid + (i << 8);
            int r = idx >> 3, seg = idx & 7;
            size_t goff = (size_t)(kt * 64 + r) * DHc + seg * 8;
            uint32_t soff = (uint32_t)(st * KVTILE * 4 + r * KVROWB + seg * 16);
            cpa16(sKu + soff, kbase + goff);
            cpa16(sVu + soff, vbase + goff);
        }
        asm volatile("cp.async.commit_group;");
    };

    float l0 = 0.f, l1 = 0.f;
    float o[8][4];
#pragma unroll
    for (int nt = 0; nt < 8; nt++)
#pragma unroll
        for (int q = 0; q < 4; q++) o[nt][q] = 0.f;

    issueKV(0, 0);
    if (tid < 64) smsk[0][tid] = src_mask[b * Lc + tid];

    for (int kt = 0; kt < 16; kt++) {
        const int st = kt & 1;
        asm volatile("cp.async.wait_group 0;");
        __syncthreads();
        if (kt + 1 < 16) {
            issueKV(kt + 1, st ^ 1);
            if (tid < 64) smsk[st ^ 1][tid] = src_mask[b * Lc + (kt + 1) * 64 + tid];
        }

        // ---- S = Q K^T ----
        float s[8][4];
        const uint32_t sKb = sKu + st * KVTILE * 4;
#pragma unroll
        for (int jt = 0; jt < 8; jt++) {
#pragma unroll
            for (int q = 0; q < 4; q++) s[jt][q] = 0.f;
            uint32_t kb[4][2];
            uint32_t base = sKb + jt * 8 * KVROWB + kOff;
            LDSM_X4(kb[0][0], kb[0][1], kb[1][0], kb[1][1], base);
            LDSM_X4(kb[2][0], kb[2][1], kb[3][0], kb[3][1], base + 64);
#pragma unroll
            for (int kk = 0; kk < 4; kk++)
                mma16816(s[jt], q0f[kk], kb[kk]);
        }

        // ---- p = mask ? exp(s*bias) : 0 ----
        const int kc0 = kt * 64;
#pragma unroll
        for (int jt = 0; jt < 8; jt++) {
            int col = jt * 8 + 2 * t;
            float2 bi0 = *(const float2*)(brow0 + kc0 + col);
            float2 bi1 = *(const float2*)(brow1 + kc0 + col);
            int mk0 = smsk[st][col], mk1 = smsk[st][col + 1];
            s[jt][0] = mk0 ? __expf(s[jt][0] * bi0.x) : 0.f;
            s[jt][1] = mk1 ? __expf(s[jt][1] * bi0.y) : 0.f;
            s[jt][2] = mk0 ? __expf(s[jt][2] * bi1.x) : 0.f;
            s[jt][3] = mk1 ? __expf(s[jt][3] * bi1.y) : 0.f;
            l0 += s[jt][0] + s[jt][1];
            l1 += s[jt][2] + s[jt][3];
        }

        // ---- O += P V ----
        const uint32_t sVb = sVu + st * KVTILE * 4;
#pragma unroll
        for (int kk = 0; kk < 4; kk++) {
            uint32_t pa0[4];
            pa0[0] = pk_f16x2(s[2 * kk][0], s[2 * kk][1]);
            pa0[1] = pk_f16x2(s[2 * kk][2], s[2 * kk][3]);
            pa0[2] = pk_f16x2(s[2 * kk + 1][0], s[2 * kk + 1][1]);
            pa0[3] = pk_f16x2(s[2 * kk + 1][2], s[2 * kk + 1][3]);
            uint32_t vb[8][2];
            uint32_t base = sVb + kk * 16 * KVROWB + vOff;
#pragma unroll
            for (int q = 0; q < 4; q++)
                LDSM_X4_T(vb[2 * q][0], vb[2 * q][1], vb[2 * q + 1][0], vb[2 * q + 1][1],
                          base + q * 32);
#pragma unroll
            for (int nt = 0; nt < 8; nt++)
                mma16816(o[nt], pa0, vb[nt]);
        }
    }

    // ---- reduce l across quad, write ctx fp16 to [B,L,D] ----
    l0 += __shfl_xor_sync(0xffffffffu, l0, 1);
    l0 += __shfl_xor_sync(0xffffffffu, l0, 2);
    l1 += __shfl_xor_sync(0xffffffffu, l1, 1);
    l1 += __shfl_xor_sync(0xffffffffu, l1, 2);
    const float inv0 = 1.f / l0, inv1 = 1.f / l1;
    const size_t ro0 = ((size_t)b * Lc + warp_q + g) * Dc + head * DHc;
    const size_t ro1 = ((size_t)b * Lc + warp_q + g + 8) * Dc + head * DHc;
#pragma unroll
    for (int nt = 0; nt < 8; nt++) {
        int col = nt * 8 + 2 * t;
        *(uint32_t*)(c0g + ro0 + col) = pk_f16x2(o[nt][0] * inv0, o[nt][1] * inv0);
        *(uint32_t*)(c0g + ro1 + col) = pk_f16x2(o[nt][2] * inv1, o[nt][3] * inv1);
    }
}

// ---------------- add + LayerNorm (float4, optional fp16 emit) ----------------
template<bool EMIT>
__global__ __launch_bounds__(256) void add_ln_k(
    const float* __restrict__ X, const float* __restrict__ Y,
    const float* __restrict__ gamma, const float* __restrict__ beta,
    float* __restrict__ out, __half* __restrict__ O0)
{
    __shared__ float sm1[8], sm2[8];
    const int row = blockIdx.x;
    const int tid = threadIdx.x;
    const int c4 = tid * 4;
    const float* x = X + (size_t)row * Dc;
    const float* y = Y + (size_t)row * Dc;

    float4 xv = *(const float4*)(x + c4);
    float4 yv = *(const float4*)(y + c4);
    float v[4] = {xv.x + yv.x, xv.y + yv.y, xv.z + yv.z, xv.w + yv.w};
    float s = v[0] + v[1] + v[2] + v[3];
    float s2 = v[0]*v[0] + v[1]*v[1] + v[2]*v[2] + v[3]*v[3];
#pragma unroll
    for (int off = 16; off >= 1; off >>= 1) {
        s  += __shfl_xor_sync(0xffffffffu, s,  off);
        s2 += __shfl_xor_sync(0xffffffffu, s2, off);
    }
    if ((tid & 31) == 0) { sm1[tid >> 5] = s; sm2[tid >> 5] = s2; }
    __syncthreads();
    s = 0.f; s2 = 0.f;
#pragma unroll
    for (int w = 0; w < 8; w++) { s += sm1[w]; s2 += sm2[w]; }

    const float invN = 1.f / (float)Dc;
    float mean = s * invN;
    float var  = s2 * invN - mean * mean;
    float rstd = rsqrtf(var + 1e-12f);

    float4 gv = *(const float4*)(gamma + c4);
    float4 bv = *(const float4*)(beta + c4);
    float o0 = gv.x * (v[0] - mean) * rstd + bv.x;
    float o1 = gv.y * (v[1] - mean) * rstd + bv.y;
    float o2 = gv.z * (v[2] - mean) * rstd + bv.z;
    float o3 = gv.w * (v[3] - mean) * rstd + bv.w;
    float4 ov; ov.x = o0; ov.y = o1; ov.z = o2; ov.w = o3;
    *(float4*)(out + (size_t)row * Dc + c4) = ov;
    if (EMIT) {
        uint2 h2;
        h2.x = pk_f16x2(o0, o1);
        h2.y = pk_f16x2(o2, o3);
        *(uint2*)(O0 + (size_t)row * Dc + c4) = h2;
    }
}

// ---------------- launch ----------------
extern "C" void kernel_launch(void* const* d_in, const int* in_sizes, int n_in,
                              void* d_out, int out_size)
{
    const float* x         = (const float*)d_in[0];
    const float* attn_bias = (const float*)d_in[1];
    const int*   src_mask  = (const int*)  d_in[2];
    const float* wq = (const float*)d_in[3];
    const float* bq = (const float*)d_in[4];
    const float* wk = (const float*)d_in[5];
    const float* bk = (const float*)d_in[6];
    const float* wv = (const float*)d_in[7];
    const float* bv = (const float*)d_in[8];
    const float* wo = (const float*)d_in[9];
    const float* bo = (const float*)d_in[10];
    const float* gamma1 = (const float*)d_in[11];
    const float* beta1  = (const float*)d_in[12];
    const float* w1 = (const float*)d_in[13];
    const float* b1 = (const float*)d_in[14];
    const float* w2 = (const float*)d_in[15];
    const float* b2 = (const float*)d_in[16];
    const float* gamma2 = (const float*)d_in[17];
    const float* beta2  = (const float*)d_in[18];
    float* out = (float*)d_out;

    float *tmp, *h, *bqkv;
    cudaGetSymbolAddress((void**)&tmp,  g_tmp);
    cudaGetSymbolAddress((void**)&h,    g_h);
    cudaGetSymbolAddress((void**)&bqkv, g_bqkv);
    __half *qkv0, *x0, *c0, *h0, *mid0;
    cudaGetSymbolAddress((void**)&qkv0, g_qkv0);
    cudaGetSymbolAddress((void**)&x0, g_x0);
    cudaGetSymbolAddress((void**)&c0, g_c0);
    cudaGetSymbolAddress((void**)&h0, g_h0);
    cudaGetSymbolAddress((void**)&mid0, g_mid0);
    __half *wqkv, *woh, *w1t, *w2t;
    cudaGetSymbolAddress((void**)&wqkv, g_wqkv);
    cudaGetSymbolAddress((void**)&woh, g_wo);
    cudaGetSymbolAddress((void**)&w1t, g_w1t);
    cudaGetSymbolAddress((void**)&w2t, g_w2t);

    cudaFuncSetAttribute(gemm1<0>, cudaFuncAttributeMaxDynamicSharedMemorySize, GSMEM);
    cudaFuncSetAttribute(gemm1<1>, cudaFuncAttributeMaxDynamicSharedMemorySize, GSMEM);
    cudaFuncSetAttribute(gemm1<2>, cudaFuncAttributeMaxDynamicSharedMemorySize, GSMEM);

    dim3 blk(256);
    dim3 gblk(288);

    // fused prep: weight transposes + x convert + bias concat (one launch)
    prep_k<<<16396, blk>>>(wq, wk, wv, wo, w1, w2, bq, bk, bv, x,
                           wqkv, woh, w1t, w2t, bqkv, x0);

    // fused QKV projection (N=3072): emits fp16 q(.125x),k,v in [B,H,L,DH]
    gemm1<1><<<dim3(3 * Dc / 128, Mrows / 128), gblk, GSMEM>>>(
        x0, wqkv, bqkv, nullptr, qkv0, Dc, 3 * Dc);

    // MMA flash attention -> ctx fp16 c0 [B,L,D]
    attn_mma_k<<<dim3(Lc / 128, Bc * Hc), blk>>>(
        qkv0, attn_bias, src_mask, c0);

    // output projection
    gemm1<0><<<dim3(Dc / 128, Mrows / 128), gblk, GSMEM>>>(
        c0, woh, bo, tmp, nullptr, Dc, Dc);

    // residual + LN1 (emit h fp32 + fp16)
    add_ln_k<true><<<Mrows, blk>>>(x, tmp, gamma1, beta1, h, h0);

    // FFN
    gemm1<2><<<dim3(FFc / 128, Mrows / 128), gblk, GSMEM>>>(
        h0, w1t, b1, nullptr, mid0, Dc, FFc);
    gemm1<0><<<dim3(Dc / 128, Mrows / 128), gblk, GSMEM>>>(
        mid0, w2t, b2, tmp, nullptr, FFc, Dc);

    // residual + LN2 -> output
    add_ln_k<false><<<Mrows, blk>>>(h, tmp, gamma2, beta2, out, nullptr);
}